// round 4
// baseline (speedup 1.0000x reference)
#include <cuda_runtime.h>

#define BN   4
#define NPTS 16384
#define MPTS 2048
#define GMAXB 8192
#define FULLM 0xffffffffu

__device__ float  g_bufA[128ull * 524288];
__device__ float  g_bufB[128ull * 524288];
__device__ float  g_featT[(size_t)BN * NPTS * 64];
__device__ float  g_newxyz[BN * 3 * MPTS];
__device__ int    g_fpsidx[BN * MPTS];
__device__ int    g_ballidx[(size_t)BN * MPTS * 64];
__device__ float  g_psum[128 * GMAXB];
__device__ float  g_psqs[128 * GMAXB];
__device__ float  g_scaleb[3 * 128];
__device__ float  g_shiftb[3 * 128];
__device__ float4 g_pts[(size_t)BN * NPTS];   // Morton-sorted (x,y,z,orig)

// ---------------- bucket prep: Morton counting sort (16^3 cells) -------------
__device__ __forceinline__ int cell_of(float x, float y, float z)
{
    int ix = min(15, max(0, (int)(x * 16.0f)));
    int iy = min(15, max(0, (int)(y * 16.0f)));
    int iz = min(15, max(0, (int)(z * 16.0f)));
    int m = 0;
#pragma unroll
    for (int k = 0; k < 4; k++)
        m |= ((ix >> k) & 1) << (3 * k) | ((iy >> k) & 1) << (3 * k + 1) |
             ((iz >> k) & 1) << (3 * k + 2);
    return m;
}

__global__ __launch_bounds__(512)
void bucket_prep(const float* __restrict__ xyz, float4* __restrict__ pts)
{
    const int b = blockIdx.x;
    const float* xb = xyz + (size_t)b * 3 * NPTS;
    __shared__ int hist[4096];
    __shared__ int wsum[16];
    const int t = threadIdx.x, lane = t & 31, wid = t >> 5;

    for (int c = t; c < 4096; c += 512) hist[c] = 0;
    __syncthreads();
    for (int j = 0; j < 32; j++) {
        int id = j * 512 + t;
        atomicAdd(&hist[cell_of(xb[id], xb[NPTS + id], xb[2 * NPTS + id])], 1);
    }
    __syncthreads();
    // exclusive scan of hist[4096]: 8 cells per thread
    int base = t * 8, s = 0, loc[8];
#pragma unroll
    for (int i = 0; i < 8; i++) { loc[i] = s; s += hist[base + i]; }
    int v = s;
#pragma unroll
    for (int o = 1; o < 32; o <<= 1) {
        int u = __shfl_up_sync(FULLM, v, o);
        if (lane >= o) v += u;
    }
    if (lane == 31) wsum[wid] = v;
    __syncthreads();
    int wOff = 0;
    for (int w = 0; w < wid; w++) wOff += wsum[w];
    int texcl = wOff + v - s;
    __syncthreads();
#pragma unroll
    for (int i = 0; i < 8; i++) hist[base + i] = texcl + loc[i];
    __syncthreads();
    for (int j = 0; j < 32; j++) {
        int id = j * 512 + t;
        float x = xb[id], y = xb[NPTS + id], z = xb[2 * NPTS + id];
        int pos = atomicAdd(&hist[cell_of(x, y, z)], 1);
        pts[(size_t)b * NPTS + pos] = make_float4(x, y, z, __int_as_float(id));
    }
}

// ---------------- pruned FPS: 512 buckets x 32 pts, exact jnp arithmetic -----
__global__ __launch_bounds__(512, 1)
void fps2_kernel(const float4* __restrict__ pts, const float* __restrict__ xyz,
                 int* __restrict__ fpsidx)
{
    const int b = blockIdx.x;
    const float4* pb = pts + (size_t)b * NPTS;
    extern __shared__ float sm[];
    float* sdist = sm;                          // NPTS
    float* sbv   = sm + NPTS;                   // 512
    int*   sbg   = (int*)(sm + NPTS + 512);     // 512 best orig idx
    int*   sbp   = (int*)(sm + NPTS + 1024);    // 512 best sorted pos
    int*   slist = (int*)(sm + NPTS + 1536);    // 512
    float* rv    = sm + NPTS + 2048;            // 16
    int*   rg    = (int*)(sm + NPTS + 2064);    // 16
    int*   rp    = (int*)(sm + NPTS + 2080);    // 16
    int*   scnt  = (int*)(sm + NPTS + 2096);    // 2
    float* slast = sm + NPTS + 2100;            // 4 (16B aligned)

    const int t = threadIdx.x, lane = t & 31, wid = t >> 5;

    // init: bbox of own bucket, dist = 1e10
    float lox = 1e30f, loy = 1e30f, loz = 1e30f;
    float hix = -1e30f, hiy = -1e30f, hiz = -1e30f;
#pragma unroll 8
    for (int j = 0; j < 32; j++) {
        float4 w = pb[t * 32 + j];
        lox = fminf(lox, w.x); hix = fmaxf(hix, w.x);
        loy = fminf(loy, w.y); hiy = fmaxf(hiy, w.y);
        loz = fminf(loz, w.z); hiz = fmaxf(hiz, w.z);
        sdist[t * 32 + j] = 1e10f;
    }
    sbv[t] = 1e10f; sbg[t] = 0x7fffffff; sbp[t] = 0;
    if (t == 0) {
        fpsidx[b * MPTS] = 0;
        slast[0] = xyz[(size_t)b * 3 * NPTS];
        slast[1] = xyz[(size_t)b * 3 * NPTS + NPTS];
        slast[2] = xyz[(size_t)b * 3 * NPTS + 2 * NPTS];
        scnt[0] = 0; scnt[1] = 0;
    }
    __syncthreads();

    for (int m = 1; m < MPTS; m++) {
        const float lx = slast[0], ly = slast[1], lz = slast[2];
        // skip test (conservative lower bound on d^2 to bbox)
        float dx = fmaxf(fmaxf(lox - lx, lx - hix), 0.0f);
        float dy = fmaxf(fmaxf(loy - ly, ly - hiy), 0.0f);
        float dz = fmaxf(fmaxf(loz - lz, lz - hiz), 0.0f);
        float d2m = dx * dx + dy * dy + dz * dz;
        bool upd = (0.999f * d2m < sbv[t]);
        unsigned mk = __ballot_sync(FULLM, upd);
        int wb = 0;
        if (lane == 0 && mk) wb = atomicAdd(&scnt[m & 1], __popc(mk));
        wb = __shfl_sync(FULLM, wb, 0);
        if (upd) slist[wb + __popc(mk & ((1u << lane) - 1u))] = t;
        __syncthreads();                                   // B1
        int U = scnt[m & 1];
        if (t == 0) scnt[(m + 1) & 1] = 0;
        if (t < U) {
            int bk = slist[t];
            int base = bk * 32;
            float bv = -1.0f; int bg = 0x7fffffff; int bp = base;
#pragma unroll 8
            for (int j = 0; j < 32; j++) {
                float4 w = pb[base + j];
                float ddx = __fsub_rn(w.x, lx);
                float ddy = __fsub_rn(w.y, ly);
                float ddz = __fsub_rn(w.z, lz);
                float d = __fadd_rn(__fadd_rn(__fmul_rn(ddx, ddx), __fmul_rn(ddy, ddy)),
                                    __fmul_rn(ddz, ddz));
                float nd = fminf(sdist[base + j], d);
                sdist[base + j] = nd;
                int orig = __float_as_int(w.w);
                if (nd > bv)                 { bv = nd; bg = orig; bp = base + j; }
                else if (nd == bv && orig < bg) { bg = orig; bp = base + j; }
            }
            sbv[bk] = bv; sbg[bk] = bg; sbp[bk] = bp;
        }
        __syncthreads();                                   // B2
        // global reduce over 512 buckets: (max value, tie -> min orig idx)
        float v = sbv[t]; int g = sbg[t]; int p = sbp[t];
#pragma unroll
        for (int o = 16; o; o >>= 1) {
            float ov = __shfl_xor_sync(FULLM, v, o);
            int   og = __shfl_xor_sync(FULLM, g, o);
            int   op = __shfl_xor_sync(FULLM, p, o);
            if (ov > v || (ov == v && og < g)) { v = ov; g = og; p = op; }
        }
        if (lane == 0) { rv[wid] = v; rg[wid] = g; rp[wid] = p; }
        __syncthreads();                                   // B3
        float v2 = (lane < 16) ? rv[lane] : -1e30f;
        int   g2 = (lane < 16) ? rg[lane] : 0x7fffffff;
        int   p2 = (lane < 16) ? rp[lane] : 0;
#pragma unroll
        for (int o = 8; o; o >>= 1) {
            float ov = __shfl_xor_sync(FULLM, v2, o);
            int   og = __shfl_xor_sync(FULLM, g2, o);
            int   op = __shfl_xor_sync(FULLM, p2, o);
            if (ov > v2 || (ov == v2 && og < g2)) { v2 = ov; g2 = og; p2 = op; }
        }
        if (t == 0) {
            fpsidx[b * MPTS + m] = g2;
            float4 w = pb[p2];
            slast[0] = w.x; slast[1] = w.y; slast[2] = w.z;
        }
        __syncthreads();                                   // B4
    }
}

// ---------------- gather new_xyz + write output head -------------------------
__global__ void newxyz_kernel(const float* __restrict__ xyz, const int* __restrict__ fpsidx,
                              float* __restrict__ nx, float* __restrict__ outh)
{
    int e = blockIdx.x * blockDim.x + threadIdx.x;
    if (e >= BN * 3 * MPTS) return;
    int m = e % MPTS, d = (e / MPTS) % 3, b = e / (3 * MPTS);
    float v = xyz[((size_t)b * 3 + d) * NPTS + fpsidx[b * MPTS + m]];
    nx[e] = v; outh[e] = v;
}

// ---------------- feature transpose [B,C,N] -> [B,N,C] -----------------------
__global__ void transpose_feat(const float* __restrict__ f, float* __restrict__ ft)
{
    __shared__ float s[32][33];
    int n0 = blockIdx.x * 32, c0 = blockIdx.y * 32, b = blockIdx.z;
    int tx = threadIdx.x, ty = threadIdx.y;
    for (int i = ty; i < 32; i += 8)
        s[i][tx] = f[((size_t)b * 64 + c0 + i) * NPTS + n0 + tx];
    __syncthreads();
    for (int i = ty; i < 32; i += 8)
        ft[((size_t)b * NPTS + n0 + i) * 64 + c0 + tx] = s[tx][i];
}

// ---------------- ball query: warp per center, ordered first-K ---------------
__global__ void ball_kernel(const float* __restrict__ xyz, const float* __restrict__ nx,
                            int* __restrict__ bidx, float r2, int K)
{
    int cid = blockIdx.x * (blockDim.x >> 5) + (threadIdx.x >> 5);
    if (cid >= BN * MPTS) return;
    int lane = threadIdx.x & 31;
    int b = cid / MPTS, m = cid % MPTS;
    const float* xb = xyz + (size_t)b * 3 * NPTS;
    float cx = nx[((size_t)b * 3 + 0) * MPTS + m];
    float cy = nx[((size_t)b * 3 + 1) * MPTS + m];
    float cz = nx[((size_t)b * 3 + 2) * MPTS + m];
    float sqc = __fadd_rn(__fadd_rn(__fmul_rn(cx, cx), __fmul_rn(cy, cy)), __fmul_rn(cz, cz));
    int cnt = 0, first = 0;
    int* op = bidx + (size_t)cid * K;
    for (int n0 = 0; n0 < NPTS; n0 += 32) {
        int n = n0 + lane;
        float x = xb[n], y = xb[NPTS + n], z = xb[2 * NPTS + n];
        float sqx = __fadd_rn(__fadd_rn(__fmul_rn(x, x), __fmul_rn(y, y)), __fmul_rn(z, z));
        float dot = __fmaf_rn(z, cz, __fmaf_rn(y, cy, __fmul_rn(x, cx)));
        float d2  = __fsub_rn(__fadd_rn(sqc, sqx), __fmul_rn(2.0f, dot));
        bool in = d2 < r2;
        unsigned mk = __ballot_sync(0xffffffffu, in);
        if (cnt == 0 && mk) first = n0 + __ffs(mk) - 1;
        if (in) {
            int pos = cnt + __popc(mk & ((1u << lane) - 1u));
            if (pos < K) op[pos] = n;
        }
        cnt += __popc(mk);
        if (cnt >= K) break;
    }
    if (cnt < K)
        for (int j = cnt + lane; j < K; j += 32) op[j] = (cnt == 0) ? 0 : first;
}

// ---------------- grouping: build X [67, P], p = cid*K + k -------------------
__global__ void group_kernel(const float* __restrict__ xyz, const float* __restrict__ featT,
                             const float* __restrict__ nx, const int* __restrict__ bidx,
                             float* __restrict__ X, int K, int P)
{
    int cid = blockIdx.x;
    int b = cid / MPTS, m = cid % MPTS;
    int k = threadIdx.x;               // blockDim == K
    __shared__ float s[67 * 64];
    int i = bidx[(size_t)cid * K + k];
    const float* xb = xyz + (size_t)b * 3 * NPTS;
    s[0 * K + k] = xb[i]            - nx[((size_t)b * 3 + 0) * MPTS + m];
    s[1 * K + k] = xb[NPTS + i]     - nx[((size_t)b * 3 + 1) * MPTS + m];
    s[2 * K + k] = xb[2 * NPTS + i] - nx[((size_t)b * 3 + 2) * MPTS + m];
    const float4* fr = (const float4*)(featT + ((size_t)b * NPTS + i) * 64);
#pragma unroll
    for (int c4 = 0; c4 < 16; c4++) {
        float4 v = fr[c4];
        int c = 3 + c4 * 4;
        s[(c + 0) * K + k] = v.x; s[(c + 1) * K + k] = v.y;
        s[(c + 2) * K + k] = v.z; s[(c + 3) * K + k] = v.w;
    }
    __syncthreads();
    size_t base = (size_t)cid * K;
    for (int e = k; e < 67 * K; e += K)
        X[(size_t)(e / K) * P + base + (e % K)] = s[e];
}

// ---------------- conv (1x1), fused input BN-affine+relu, stat partials ------
template <int OT>   // Cout = OT*16
__global__ __launch_bounds__(256)
void conv_kernel(const float* __restrict__ X, const float* __restrict__ W,
                 const float* __restrict__ inS, const float* __restrict__ inB,
                 float* __restrict__ Y, float* __restrict__ pSum, float* __restrict__ pSqs,
                 int Cin, int P)
{
    const int Cout = OT * 16;
    __shared__ float sW[16][OT * 16 + 4];
    __shared__ float sX[16][68];
    __shared__ float sR[OT * 16 * 16];
    int tid = threadIdx.x;
    int pp = tid & 15, og = tid >> 4;
    int pbase = blockIdx.x * 64;

    float acc[OT][4];
#pragma unroll
    for (int i = 0; i < OT; i++)
#pragma unroll
        for (int j = 0; j < 4; j++) acc[i][j] = 0.0f;

    for (int c0 = 0; c0 < Cin; c0 += 16) {
        int rem = Cin - c0;
        for (int e = tid; e < Cout * 16; e += 256) {
            int o = e >> 4, cc = e & 15;
            sW[cc][o] = (cc < rem) ? W[(size_t)o * Cin + c0 + cc] : 0.0f;
        }
        {
            int cc = tid >> 4, p4 = tid & 15;
            float4 v = make_float4(0.f, 0.f, 0.f, 0.f);
            if (cc < rem) {
                v = *(const float4*)(X + (size_t)(c0 + cc) * P + pbase + p4 * 4);
                if (inS) {
                    float sc = inS[c0 + cc], sh = inB[c0 + cc];
                    v.x = fmaxf(fmaf(v.x, sc, sh), 0.f);
                    v.y = fmaxf(fmaf(v.y, sc, sh), 0.f);
                    v.z = fmaxf(fmaf(v.z, sc, sh), 0.f);
                    v.w = fmaxf(fmaf(v.w, sc, sh), 0.f);
                }
            }
            ((float4*)&sX[cc][0])[p4] = v;
        }
        __syncthreads();
#pragma unroll
        for (int cc = 0; cc < 16; cc++) {
            float4 xv = ((float4*)&sX[cc][0])[pp];
#pragma unroll
            for (int i = 0; i < OT; i++) {
                float wv = sW[cc][og * OT + i];
                acc[i][0] = fmaf(wv, xv.x, acc[i][0]);
                acc[i][1] = fmaf(wv, xv.y, acc[i][1]);
                acc[i][2] = fmaf(wv, xv.z, acc[i][2]);
                acc[i][3] = fmaf(wv, xv.w, acc[i][3]);
            }
        }
        __syncthreads();
    }
#pragma unroll
    for (int i = 0; i < OT; i++)
        *(float4*)(Y + (size_t)(og * OT + i) * P + pbase + pp * 4) =
            make_float4(acc[i][0], acc[i][1], acc[i][2], acc[i][3]);
#pragma unroll
    for (int i = 0; i < OT; i++)
        sR[(og * OT + i) * 16 + pp] = acc[i][0] + acc[i][1] + acc[i][2] + acc[i][3];
    __syncthreads();
    for (int o = tid; o < Cout; o += 256) {
        float s = 0.f;
#pragma unroll
        for (int j = 0; j < 16; j++) s += sR[o * 16 + j];
        pSum[(size_t)o * GMAXB + blockIdx.x] = s;
    }
    __syncthreads();
#pragma unroll
    for (int i = 0; i < OT; i++)
        sR[(og * OT + i) * 16 + pp] = acc[i][0] * acc[i][0] + acc[i][1] * acc[i][1] +
                                      acc[i][2] * acc[i][2] + acc[i][3] * acc[i][3];
    __syncthreads();
    for (int o = tid; o < Cout; o += 256) {
        float s = 0.f;
#pragma unroll
        for (int j = 0; j < 16; j++) s += sR[o * 16 + j];
        pSqs[(size_t)o * GMAXB + blockIdx.x] = s;
    }
}

// ---------------- BN stats -> per-channel scale/shift ------------------------
__global__ void stats_kernel(const float* __restrict__ pSum, const float* __restrict__ pSqs,
                             int nb, float invP, const float* __restrict__ g,
                             const float* __restrict__ bta,
                             float* __restrict__ sc, float* __restrict__ sh)
{
    int o = blockIdx.x;
    __shared__ float sa[256], sb[256];
    int t = threadIdx.x;
    float s = 0.f, q = 0.f;
    for (int j = t; j < nb; j += 256) {
        s += pSum[(size_t)o * GMAXB + j];
        q += pSqs[(size_t)o * GMAXB + j];
    }
    sa[t] = s; sb[t] = q; __syncthreads();
    for (int st = 128; st; st >>= 1) {
        if (t < st) { sa[t] += sa[t + st]; sb[t] += sb[t + st]; }
        __syncthreads();
    }
    if (t == 0) {
        float mu = sa[0] * invP;
        float var = sb[0] * invP - mu * mu;
        float scale = g[o] * rsqrtf(var + 1e-5f);
        sc[o] = scale;
        sh[o] = bta[o] - mu * scale;
    }
}

// ---------------- final: affine+relu then max over K -------------------------
__global__ void finalmax_kernel(const float* __restrict__ Y, const float* __restrict__ sc,
                                const float* __restrict__ sh, float* __restrict__ out,
                                int K, int P, int ochoff)
{
    int e = blockIdx.x * blockDim.x + threadIdx.x;
    if (e >= BN * 128 * MPTS) return;
    int m = e % MPTS, o = (e / MPTS) & 127, b = e / (128 * MPTS);
    const float* yp = Y + (size_t)o * P + (size_t)((size_t)b * MPTS + m) * K;
    float scale = sc[o], shift = sh[o];
    float best = 0.0f;
    for (int k = 0; k < K; k++)
        best = fmaxf(best, fmaxf(fmaf(yp[k], scale, shift), 0.f));
    out[((size_t)b * 256 + ochoff + o) * MPTS + m] = best;
}

// ---------------- host orchestration -----------------------------------------
extern "C" void kernel_launch(void* const* d_in, const int* in_sizes, int n_in,
                              void* d_out, int out_size)
{
    const float* xyz  = (const float*)d_in[0];
    const float* feat = (const float*)d_in[1];
    auto Wp = [&](int s, int l) { return (const float*)d_in[2 + s * 9 + l * 3 + 0]; };
    auto Gp = [&](int s, int l) { return (const float*)d_in[2 + s * 9 + l * 3 + 1]; };
    auto Bp = [&](int s, int l) { return (const float*)d_in[2 + s * 9 + l * 3 + 2]; };

    float* bufA; cudaGetSymbolAddress((void**)&bufA, g_bufA);
    float* bufB; cudaGetSymbolAddress((void**)&bufB, g_bufB);
    float* featT; cudaGetSymbolAddress((void**)&featT, g_featT);
    float* nx;   cudaGetSymbolAddress((void**)&nx, g_newxyz);
    int*   fpsi; cudaGetSymbolAddress((void**)&fpsi, g_fpsidx);
    int*   bidx; cudaGetSymbolAddress((void**)&bidx, g_ballidx);
    float* pSum; cudaGetSymbolAddress((void**)&pSum, g_psum);
    float* pSqs; cudaGetSymbolAddress((void**)&pSqs, g_psqs);
    float* scb;  cudaGetSymbolAddress((void**)&scb, g_scaleb);
    float* shb;  cudaGetSymbolAddress((void**)&shb, g_shiftb);
    float4* pts; cudaGetSymbolAddress((void**)&pts, g_pts);

    float* out  = (float*)d_out;

    const int fps_smem = (NPTS + 2112) * 4;
    cudaFuncSetAttribute(fps2_kernel, cudaFuncAttributeMaxDynamicSharedMemorySize, fps_smem);

    bucket_prep<<<BN, 512>>>(xyz, pts);
    fps2_kernel<<<BN, 512, fps_smem>>>(pts, xyz, fpsi);
    newxyz_kernel<<<(BN * 3 * MPTS + 255) / 256, 256>>>(xyz, fpsi, nx, out);
    transpose_feat<<<dim3(NPTS / 32, 2, BN), dim3(32, 8)>>>(feat, featT);

    const int   KS_[2]  = {32, 64};
    const float R2_[2]  = {0.04f, 0.16f};
    const int   CH_[2][3] = {{64, 64, 128}, {64, 96, 128}};

    for (int s = 0; s < 2; s++) {
        int K = KS_[s];
        int P = BN * MPTS * K;
        int nb = P / 64;
        ball_kernel<<<(BN * MPTS + 7) / 8, 256>>>(xyz, nx, bidx, R2_[s], K);
        group_kernel<<<BN * MPTS, K>>>(xyz, featT, nx, bidx, bufA, K, P);

        float* Xc = bufA; float* Yc = bufB;
        int Cin = 67;
        for (int l = 0; l < 3; l++) {
            int Cout = CH_[s][l];
            const float* inS = (l == 0) ? nullptr : scb + (l - 1) * 128;
            const float* inB = (l == 0) ? nullptr : shb + (l - 1) * 128;
            if (Cout == 64)
                conv_kernel<4><<<nb, 256>>>(Xc, Wp(s, l), inS, inB, Yc, pSum, pSqs, Cin, P);
            else if (Cout == 96)
                conv_kernel<6><<<nb, 256>>>(Xc, Wp(s, l), inS, inB, Yc, pSum, pSqs, Cin, P);
            else
                conv_kernel<8><<<nb, 256>>>(Xc, Wp(s, l), inS, inB, Yc, pSum, pSqs, Cin, P);
            stats_kernel<<<Cout, 256>>>(pSum, pSqs, nb, 1.0f / (float)P,
                                        Gp(s, l), Bp(s, l), scb + l * 128, shb + l * 128);
            float* t = Xc; Xc = Yc; Yc = t;
            Cin = Cout;
        }
        finalmax_kernel<<<(BN * 128 * MPTS + 255) / 256, 256>>>(
            Xc, scb + 2 * 128, shb + 2 * 128, out + BN * 3 * MPTS, K, P, s * 128);
    }
    (void)in_sizes; (void)n_in; (void)out_size;
}

// round 5
// speedup vs baseline: 1.4569x; 1.4569x over previous
#include <cuda_runtime.h>

#define BN   4
#define NPTS 16384
#define MPTS 2048
#define GMAXB 8192
#define FULLM 0xffffffffu

__device__ float  g_bufA[128ull * 524288];
__device__ float  g_bufB[128ull * 524288];
__device__ float  g_featT[(size_t)BN * NPTS * 64];
__device__ float  g_newxyz[BN * 3 * MPTS];
__device__ int    g_fpsidx[BN * MPTS];
__device__ int    g_ballidx[(size_t)BN * MPTS * 64];
__device__ float  g_psum[128 * GMAXB];
__device__ float  g_psqs[128 * GMAXB];
__device__ float  g_scaleb[3 * 128];
__device__ float  g_shiftb[3 * 128];
__device__ float4 g_pts[(size_t)BN * NPTS];   // Morton-sorted (x,y,z,orig)

// ---------------- bucket prep: Morton counting sort (16^3 cells) -------------
__device__ __forceinline__ int cell_of(float x, float y, float z)
{
    int ix = min(15, max(0, (int)(x * 16.0f)));
    int iy = min(15, max(0, (int)(y * 16.0f)));
    int iz = min(15, max(0, (int)(z * 16.0f)));
    int m = 0;
#pragma unroll
    for (int k = 0; k < 4; k++)
        m |= ((ix >> k) & 1) << (3 * k) | ((iy >> k) & 1) << (3 * k + 1) |
             ((iz >> k) & 1) << (3 * k + 2);
    return m;
}

__global__ __launch_bounds__(512)
void bucket_prep(const float* __restrict__ xyz, float4* __restrict__ pts)
{
    const int b = blockIdx.x;
    const float* xb = xyz + (size_t)b * 3 * NPTS;
    __shared__ int hist[4096];
    __shared__ int wsum[16];
    const int t = threadIdx.x, lane = t & 31, wid = t >> 5;

    for (int c = t; c < 4096; c += 512) hist[c] = 0;
    __syncthreads();
    for (int j = 0; j < 32; j++) {
        int id = j * 512 + t;
        atomicAdd(&hist[cell_of(xb[id], xb[NPTS + id], xb[2 * NPTS + id])], 1);
    }
    __syncthreads();
    int base = t * 8, s = 0, loc[8];
#pragma unroll
    for (int i = 0; i < 8; i++) { loc[i] = s; s += hist[base + i]; }
    int v = s;
#pragma unroll
    for (int o = 1; o < 32; o <<= 1) {
        int u = __shfl_up_sync(FULLM, v, o);
        if (lane >= o) v += u;
    }
    if (lane == 31) wsum[wid] = v;
    __syncthreads();
    int wOff = 0;
    for (int w = 0; w < wid; w++) wOff += wsum[w];
    int texcl = wOff + v - s;
    __syncthreads();
#pragma unroll
    for (int i = 0; i < 8; i++) hist[base + i] = texcl + loc[i];
    __syncthreads();
    for (int j = 0; j < 32; j++) {
        int id = j * 512 + t;
        float x = xb[id], y = xb[NPTS + id], z = xb[2 * NPTS + id];
        int pos = atomicAdd(&hist[cell_of(x, y, z)], 1);
        pts[(size_t)b * NPTS + pos] = make_float4(x, y, z, __int_as_float(id));
    }
}

// ---------------- pruned FPS v2: warp-per-bucket update ----------------------
__global__ __launch_bounds__(512, 1)
void fps2_kernel(const float4* __restrict__ pts, const float* __restrict__ xyz,
                 int* __restrict__ fpsidx)
{
    const int b = blockIdx.x;
    const float4* pb = pts + (size_t)b * NPTS;
    extern __shared__ float sm[];
    float* sdist = sm;                          // NPTS
    float* sbv   = sm + NPTS;                   // 512 bucket max(min-dist)
    int*   sbg   = (int*)(sm + NPTS + 512);     // 512 best orig idx
    int*   sbp   = (int*)(sm + NPTS + 1024);    // 512 best sorted pos
    int*   slist = (int*)(sm + NPTS + 1536);    // 512 compacted bucket list
    float* rv    = sm + NPTS + 2048;            // 16
    int*   rg    = (int*)(sm + NPTS + 2064);    // 16
    int*   rp    = (int*)(sm + NPTS + 2080);    // 16
    int*   scnt  = (int*)(sm + NPTS + 2096);    // 1
    float* slast = sm + NPTS + 2100;            // 4

    const int t = threadIdx.x, lane = t & 31, wid = t >> 5;

    // init: bbox of own bucket, dist = 1e10
    float lox = 1e30f, loy = 1e30f, loz = 1e30f;
    float hix = -1e30f, hiy = -1e30f, hiz = -1e30f;
#pragma unroll 8
    for (int j = 0; j < 32; j++) {
        float4 w = pb[t * 32 + j];
        lox = fminf(lox, w.x); hix = fmaxf(hix, w.x);
        loy = fminf(loy, w.y); hiy = fmaxf(hiy, w.y);
        loz = fminf(loz, w.z); hiz = fmaxf(hiz, w.z);
        sdist[t * 32 + j] = 1e10f;
    }
    sbv[t] = 1e10f; sbg[t] = 0x7fffffff; sbp[t] = 0;
    if (t == 0) {
        fpsidx[b * MPTS] = 0;
        slast[0] = xyz[(size_t)b * 3 * NPTS];
        slast[1] = xyz[(size_t)b * 3 * NPTS + NPTS];
        slast[2] = xyz[(size_t)b * 3 * NPTS + 2 * NPTS];
        scnt[0] = 0;
    }
    __syncthreads();

    for (int m = 1; m < MPTS; m++) {
        const float lx = slast[0], ly = slast[1], lz = slast[2];
        // ---- Phase A: skip test (conservative lower bound d^2 to bbox) ----
        float dx = fmaxf(fmaxf(lox - lx, lx - hix), 0.0f);
        float dy = fmaxf(fmaxf(loy - ly, ly - hiy), 0.0f);
        float dz = fmaxf(fmaxf(loz - lz, lz - hiz), 0.0f);
        float d2m = dx * dx + dy * dy + dz * dz;
        bool upd = (0.999f * d2m < sbv[t]);
        unsigned mk = __ballot_sync(FULLM, upd);
        int wb = 0;
        if (lane == 0 && mk) wb = atomicAdd(scnt, __popc(mk));
        wb = __shfl_sync(FULLM, wb, 0);
        if (upd) slist[wb + __popc(mk & ((1u << lane) - 1u))] = t;
        __syncthreads();                                   // B1
        // ---- Phase B: warp-per-bucket update, lane-per-point --------------
        int U = scnt[0];
        for (int i = wid; i < U; i += 16) {
            int bk = slist[i];
            int pos = bk * 32 + lane;
            float4 w = pb[pos];
            float ddx = __fsub_rn(w.x, lx);
            float ddy = __fsub_rn(w.y, ly);
            float ddz = __fsub_rn(w.z, lz);
            float d = __fadd_rn(__fadd_rn(__fmul_rn(ddx, ddx), __fmul_rn(ddy, ddy)),
                                __fmul_rn(ddz, ddz));
            float nd = fminf(sdist[pos], d);
            sdist[pos] = nd;
            float v = nd; int g = __float_as_int(w.w); int p = pos;
#pragma unroll
            for (int o = 16; o; o >>= 1) {
                float ov = __shfl_xor_sync(FULLM, v, o);
                int   og = __shfl_xor_sync(FULLM, g, o);
                int   op = __shfl_xor_sync(FULLM, p, o);
                if (ov > v || (ov == v && og < g)) { v = ov; g = og; p = op; }
            }
            if (lane == 0) { sbv[bk] = v; sbg[bk] = g; sbp[bk] = p; }
        }
        __syncthreads();                                   // B2
        // ---- Phase C: global reduce over 512 buckets ----------------------
        float v = sbv[t]; int g = sbg[t]; int p = sbp[t];
#pragma unroll
        for (int o = 16; o; o >>= 1) {
            float ov = __shfl_xor_sync(FULLM, v, o);
            int   og = __shfl_xor_sync(FULLM, g, o);
            int   op = __shfl_xor_sync(FULLM, p, o);
            if (ov > v || (ov == v && og < g)) { v = ov; g = og; p = op; }
        }
        if (lane == 0) { rv[wid] = v; rg[wid] = g; rp[wid] = p; }
        __syncthreads();                                   // B3
        if (t == 0) {
            float v2 = rv[0]; int g2 = rg[0]; int p2 = rp[0];
#pragma unroll
            for (int j = 1; j < 16; j++) {
                float ov = rv[j];
                if (ov > v2 || (ov == v2 && rg[j] < g2)) { v2 = ov; g2 = rg[j]; p2 = rp[j]; }
            }
            fpsidx[b * MPTS + m] = g2;
            float4 w = pb[p2];
            slast[0] = w.x; slast[1] = w.y; slast[2] = w.z;
            scnt[0] = 0;
        }
        __syncthreads();                                   // B4
    }
}

// ---------------- gather new_xyz + write output head -------------------------
__global__ void newxyz_kernel(const float* __restrict__ xyz, const int* __restrict__ fpsidx,
                              float* __restrict__ nx, float* __restrict__ outh)
{
    int e = blockIdx.x * blockDim.x + threadIdx.x;
    if (e >= BN * 3 * MPTS) return;
    int m = e % MPTS, d = (e / MPTS) % 3, b = e / (3 * MPTS);
    float v = xyz[((size_t)b * 3 + d) * NPTS + fpsidx[b * MPTS + m]];
    nx[e] = v; outh[e] = v;
}

// ---------------- feature transpose [B,C,N] -> [B,N,C] -----------------------
__global__ void transpose_feat(const float* __restrict__ f, float* __restrict__ ft)
{
    __shared__ float s[32][33];
    int n0 = blockIdx.x * 32, c0 = blockIdx.y * 32, b = blockIdx.z;
    int tx = threadIdx.x, ty = threadIdx.y;
    for (int i = ty; i < 32; i += 8)
        s[i][tx] = f[((size_t)b * 64 + c0 + i) * NPTS + n0 + tx];
    __syncthreads();
    for (int i = ty; i < 32; i += 8)
        ft[((size_t)b * NPTS + n0 + i) * 64 + c0 + tx] = s[tx][i];
}

// ---------------- ball query: warp per center, ordered first-K ---------------
__global__ void ball_kernel(const float* __restrict__ xyz, const float* __restrict__ nx,
                            int* __restrict__ bidx, float r2, int K)
{
    int cid = blockIdx.x * (blockDim.x >> 5) + (threadIdx.x >> 5);
    if (cid >= BN * MPTS) return;
    int lane = threadIdx.x & 31;
    int b = cid / MPTS, m = cid % MPTS;
    const float* xb = xyz + (size_t)b * 3 * NPTS;
    float cx = nx[((size_t)b * 3 + 0) * MPTS + m];
    float cy = nx[((size_t)b * 3 + 1) * MPTS + m];
    float cz = nx[((size_t)b * 3 + 2) * MPTS + m];
    float sqc = __fadd_rn(__fadd_rn(__fmul_rn(cx, cx), __fmul_rn(cy, cy)), __fmul_rn(cz, cz));
    int cnt = 0, first = 0;
    int* op = bidx + (size_t)cid * K;
    for (int n0 = 0; n0 < NPTS; n0 += 32) {
        int n = n0 + lane;
        float x = xb[n], y = xb[NPTS + n], z = xb[2 * NPTS + n];
        float sqx = __fadd_rn(__fadd_rn(__fmul_rn(x, x), __fmul_rn(y, y)), __fmul_rn(z, z));
        float dot = __fmaf_rn(z, cz, __fmaf_rn(y, cy, __fmul_rn(x, cx)));
        float d2  = __fsub_rn(__fadd_rn(sqc, sqx), __fmul_rn(2.0f, dot));
        bool in = d2 < r2;
        unsigned mk = __ballot_sync(0xffffffffu, in);
        if (cnt == 0 && mk) first = n0 + __ffs(mk) - 1;
        if (in) {
            int pos = cnt + __popc(mk & ((1u << lane) - 1u));
            if (pos < K) op[pos] = n;
        }
        cnt += __popc(mk);
        if (cnt >= K) break;
    }
    if (cnt < K)
        for (int j = cnt + lane; j < K; j += 32) op[j] = (cnt == 0) ? 0 : first;
}

// ---------------- grouping: build X [67, P], p = cid*K + k -------------------
__global__ void group_kernel(const float* __restrict__ xyz, const float* __restrict__ featT,
                             const float* __restrict__ nx, const int* __restrict__ bidx,
                             float* __restrict__ X, int K, int P)
{
    int cid = blockIdx.x;
    int b = cid / MPTS, m = cid % MPTS;
    int k = threadIdx.x;               // blockDim == K
    __shared__ float s[67 * 64];
    int i = bidx[(size_t)cid * K + k];
    const float* xb = xyz + (size_t)b * 3 * NPTS;
    s[0 * K + k] = xb[i]            - nx[((size_t)b * 3 + 0) * MPTS + m];
    s[1 * K + k] = xb[NPTS + i]     - nx[((size_t)b * 3 + 1) * MPTS + m];
    s[2 * K + k] = xb[2 * NPTS + i] - nx[((size_t)b * 3 + 2) * MPTS + m];
    const float4* fr = (const float4*)(featT + ((size_t)b * NPTS + i) * 64);
#pragma unroll
    for (int c4 = 0; c4 < 16; c4++) {
        float4 v = fr[c4];
        int c = 3 + c4 * 4;
        s[(c + 0) * K + k] = v.x; s[(c + 1) * K + k] = v.y;
        s[(c + 2) * K + k] = v.z; s[(c + 3) * K + k] = v.w;
    }
    __syncthreads();
    size_t base = (size_t)cid * K;
    for (int e = k; e < 67 * K; e += K)
        X[(size_t)(e / K) * P + base + (e % K)] = s[e];
}

// ---------------- conv (1x1), fused input BN-affine+relu, stat partials ------
template <int OT>   // Cout = OT*16
__global__ __launch_bounds__(256)
void conv_kernel(const float* __restrict__ X, const float* __restrict__ W,
                 const float* __restrict__ inS, const float* __restrict__ inB,
                 float* __restrict__ Y, float* __restrict__ pSum, float* __restrict__ pSqs,
                 int Cin, int P)
{
    const int Cout = OT * 16;
    __shared__ float sW[16][OT * 16 + 4];
    __shared__ float sX[16][68];
    __shared__ float sR[OT * 16 * 16];
    int tid = threadIdx.x;
    int pp = tid & 15, og = tid >> 4;
    int pbase = blockIdx.x * 64;

    float acc[OT][4];
#pragma unroll
    for (int i = 0; i < OT; i++)
#pragma unroll
        for (int j = 0; j < 4; j++) acc[i][j] = 0.0f;

    for (int c0 = 0; c0 < Cin; c0 += 16) {
        int rem = Cin - c0;
        for (int e = tid; e < Cout * 16; e += 256) {
            int o = e >> 4, cc = e & 15;
            sW[cc][o] = (cc < rem) ? W[(size_t)o * Cin + c0 + cc] : 0.0f;
        }
        {
            int cc = tid >> 4, p4 = tid & 15;
            float4 v = make_float4(0.f, 0.f, 0.f, 0.f);
            if (cc < rem) {
                v = *(const float4*)(X + (size_t)(c0 + cc) * P + pbase + p4 * 4);
                if (inS) {
                    float sc = inS[c0 + cc], sh = inB[c0 + cc];
                    v.x = fmaxf(fmaf(v.x, sc, sh), 0.f);
                    v.y = fmaxf(fmaf(v.y, sc, sh), 0.f);
                    v.z = fmaxf(fmaf(v.z, sc, sh), 0.f);
                    v.w = fmaxf(fmaf(v.w, sc, sh), 0.f);
                }
            }
            ((float4*)&sX[cc][0])[p4] = v;
        }
        __syncthreads();
#pragma unroll
        for (int cc = 0; cc < 16; cc++) {
            float4 xv = ((float4*)&sX[cc][0])[pp];
#pragma unroll
            for (int i = 0; i < OT; i++) {
                float wv = sW[cc][og * OT + i];
                acc[i][0] = fmaf(wv, xv.x, acc[i][0]);
                acc[i][1] = fmaf(wv, xv.y, acc[i][1]);
                acc[i][2] = fmaf(wv, xv.z, acc[i][2]);
                acc[i][3] = fmaf(wv, xv.w, acc[i][3]);
            }
        }
        __syncthreads();
    }
#pragma unroll
    for (int i = 0; i < OT; i++)
        *(float4*)(Y + (size_t)(og * OT + i) * P + pbase + pp * 4) =
            make_float4(acc[i][0], acc[i][1], acc[i][2], acc[i][3]);
#pragma unroll
    for (int i = 0; i < OT; i++)
        sR[(og * OT + i) * 16 + pp] = acc[i][0] + acc[i][1] + acc[i][2] + acc[i][3];
    __syncthreads();
    for (int o = tid; o < Cout; o += 256) {
        float s = 0.f;
#pragma unroll
        for (int j = 0; j < 16; j++) s += sR[o * 16 + j];
        pSum[(size_t)o * GMAXB + blockIdx.x] = s;
    }
    __syncthreads();
#pragma unroll
    for (int i = 0; i < OT; i++)
        sR[(og * OT + i) * 16 + pp] = acc[i][0] * acc[i][0] + acc[i][1] * acc[i][1] +
                                      acc[i][2] * acc[i][2] + acc[i][3] * acc[i][3];
    __syncthreads();
    for (int o = tid; o < Cout; o += 256) {
        float s = 0.f;
#pragma unroll
        for (int j = 0; j < 16; j++) s += sR[o * 16 + j];
        pSqs[(size_t)o * GMAXB + blockIdx.x] = s;
    }
}

// ---------------- BN stats -> per-channel scale/shift ------------------------
__global__ void stats_kernel(const float* __restrict__ pSum, const float* __restrict__ pSqs,
                             int nb, float invP, const float* __restrict__ g,
                             const float* __restrict__ bta,
                             float* __restrict__ sc, float* __restrict__ sh)
{
    int o = blockIdx.x;
    __shared__ float sa[256], sb[256];
    int t = threadIdx.x;
    float s = 0.f, q = 0.f;
    for (int j = t; j < nb; j += 256) {
        s += pSum[(size_t)o * GMAXB + j];
        q += pSqs[(size_t)o * GMAXB + j];
    }
    sa[t] = s; sb[t] = q; __syncthreads();
    for (int st = 128; st; st >>= 1) {
        if (t < st) { sa[t] += sa[t + st]; sb[t] += sb[t + st]; }
        __syncthreads();
    }
    if (t == 0) {
        float mu = sa[0] * invP;
        float var = sb[0] * invP - mu * mu;
        float scale = g[o] * rsqrtf(var + 1e-5f);
        sc[o] = scale;
        sh[o] = bta[o] - mu * scale;
    }
}

// ---------------- final: affine+relu then max over K -------------------------
__global__ void finalmax_kernel(const float* __restrict__ Y, const float* __restrict__ sc,
                                const float* __restrict__ sh, float* __restrict__ out,
                                int K, int P, int ochoff)
{
    int e = blockIdx.x * blockDim.x + threadIdx.x;
    if (e >= BN * 128 * MPTS) return;
    int m = e % MPTS, o = (e / MPTS) & 127, b = e / (128 * MPTS);
    const float* yp = Y + (size_t)o * P + (size_t)((size_t)b * MPTS + m) * K;
    float scale = sc[o], shift = sh[o];
    float best = 0.0f;
    for (int k = 0; k < K; k++)
        best = fmaxf(best, fmaxf(fmaf(yp[k], scale, shift), 0.f));
    out[((size_t)b * 256 + ochoff + o) * MPTS + m] = best;
}

// ---------------- host orchestration -----------------------------------------
extern "C" void kernel_launch(void* const* d_in, const int* in_sizes, int n_in,
                              void* d_out, int out_size)
{
    const float* xyz  = (const float*)d_in[0];
    const float* feat = (const float*)d_in[1];
    auto Wp = [&](int s, int l) { return (const float*)d_in[2 + s * 9 + l * 3 + 0]; };
    auto Gp = [&](int s, int l) { return (const float*)d_in[2 + s * 9 + l * 3 + 1]; };
    auto Bp = [&](int s, int l) { return (const float*)d_in[2 + s * 9 + l * 3 + 2]; };

    float* bufA; cudaGetSymbolAddress((void**)&bufA, g_bufA);
    float* bufB; cudaGetSymbolAddress((void**)&bufB, g_bufB);
    float* featT; cudaGetSymbolAddress((void**)&featT, g_featT);
    float* nx;   cudaGetSymbolAddress((void**)&nx, g_newxyz);
    int*   fpsi; cudaGetSymbolAddress((void**)&fpsi, g_fpsidx);
    int*   bidx; cudaGetSymbolAddress((void**)&bidx, g_ballidx);
    float* pSum; cudaGetSymbolAddress((void**)&pSum, g_psum);
    float* pSqs; cudaGetSymbolAddress((void**)&pSqs, g_psqs);
    float* scb;  cudaGetSymbolAddress((void**)&scb, g_scaleb);
    float* shb;  cudaGetSymbolAddress((void**)&shb, g_shiftb);
    float4* pts; cudaGetSymbolAddress((void**)&pts, g_pts);

    float* out  = (float*)d_out;

    const int fps_smem = (NPTS + 2112) * 4;
    cudaFuncSetAttribute(fps2_kernel, cudaFuncAttributeMaxDynamicSharedMemorySize, fps_smem);

    bucket_prep<<<BN, 512>>>(xyz, pts);
    fps2_kernel<<<BN, 512, fps_smem>>>(pts, xyz, fpsi);
    newxyz_kernel<<<(BN * 3 * MPTS + 255) / 256, 256>>>(xyz, fpsi, nx, out);
    transpose_feat<<<dim3(NPTS / 32, 2, BN), dim3(32, 8)>>>(feat, featT);

    const int   KS_[2]  = {32, 64};
    const float R2_[2]  = {0.04f, 0.16f};
    const int   CH_[2][3] = {{64, 64, 128}, {64, 96, 128}};

    for (int s = 0; s < 2; s++) {
        int K = KS_[s];
        int P = BN * MPTS * K;
        int nb = P / 64;
        ball_kernel<<<(BN * MPTS + 7) / 8, 256>>>(xyz, nx, bidx, R2_[s], K);
        group_kernel<<<BN * MPTS, K>>>(xyz, featT, nx, bidx, bufA, K, P);

        float* Xc = bufA; float* Yc = bufB;
        int Cin = 67;
        for (int l = 0; l < 3; l++) {
            int Cout = CH_[s][l];
            const float* inS = (l == 0) ? nullptr : scb + (l - 1) * 128;
            const float* inB = (l == 0) ? nullptr : shb + (l - 1) * 128;
            if (Cout == 64)
                conv_kernel<4><<<nb, 256>>>(Xc, Wp(s, l), inS, inB, Yc, pSum, pSqs, Cin, P);
            else if (Cout == 96)
                conv_kernel<6><<<nb, 256>>>(Xc, Wp(s, l), inS, inB, Yc, pSum, pSqs, Cin, P);
            else
                conv_kernel<8><<<nb, 256>>>(Xc, Wp(s, l), inS, inB, Yc, pSum, pSqs, Cin, P);
            stats_kernel<<<Cout, 256>>>(pSum, pSqs, nb, 1.0f / (float)P,
                                        Gp(s, l), Bp(s, l), scb + l * 128, shb + l * 128);
            float* t = Xc; Xc = Yc; Yc = t;
            Cin = Cout;
        }
        finalmax_kernel<<<(BN * 128 * MPTS + 255) / 256, 256>>>(
            Xc, scb + 2 * 128, shb + 2 * 128, out + BN * 3 * MPTS, K, P, s * 128);
    }
    (void)in_sizes; (void)n_in; (void)out_size;
}